// round 2
// baseline (speedup 1.0000x reference)
#include <cuda_runtime.h>
#include <math.h>

// Problem constants
#define LSEQ 4096
#define DD   192
#define BB   2
#define TOT  (BB*LSEQ*DD)   // 1,572,864

// ---------------- scratch (no allocations allowed) ----------------
__device__ __align__(16) float g_tokens[TOT];  // [b][l][d]
__device__ __align__(16) float g_uT[TOT];      // [b][d][l]
__device__ __align__(16) float g_Bm[TOT];      // [b][l][n]
__device__ __align__(16) float g_Cm[TOT];      // [b][l][n]
__device__ __align__(16) float g_deltaT[TOT];  // [b][d][l]
__device__ __align__(16) float g_duT[TOT];     // [b][d][l]

// ---------------- helpers ----------------
__device__ __forceinline__ float ex2f(float x) {
    float y;
    asm("ex2.approx.ftz.f32 %0, %1;" : "=f"(y) : "f"(x));
    return y;
}

__device__ __forceinline__ float softplus_f(float x) {
    // matches jax.nn.softplus = log(1 + exp(x)) to fp32 precision
    if (x > 20.0f) return x;
    return log1pf(expf(x));
}

__device__ __forceinline__ void cp16(float* smem_dst, const float* gmem_src) {
    unsigned s = (unsigned)__cvta_generic_to_shared(smem_dst);
    asm volatile("cp.async.cg.shared.global [%0], [%1], 16;\n" :: "r"(s), "l"(gmem_src));
}
__device__ __forceinline__ void cp_commit() { asm volatile("cp.async.commit_group;\n" ::: "memory"); }
__device__ __forceinline__ void cp_wait0()  { asm volatile("cp.async.wait_group 0;\n" ::: "memory"); }

// ---------------- K0: tokenize (window unfold) ----------------
// tokens[b][l][d] = x[b][c][ih*2+dy][iw*2+dx],  d=c*4+dy*2+dx, l=ih*64+iw
__global__ void remap_kernel(const float* __restrict__ x) {
    int idx = blockIdx.x * 256 + threadIdx.x;
    if (idx >= TOT) return;
    int d = idx % DD;
    int l = (idx / DD) & (LSEQ - 1);
    int b = idx / (DD * LSEQ);
    int c  = d >> 2;
    int dy = (d >> 1) & 1;
    int dx = d & 1;
    int ih = l >> 6;
    int iw = l & 63;
    float v = x[((b * 48 + c) * 128 + (ih * 2 + dy)) * 128 + (iw * 2 + dx)];
    g_tokens[idx] = v;
    g_uT[(b * DD + d) * LSEQ + l] = v;
}

// ---------------- K1: fused projections (SIMT fp32 GEMM, M=8192, N=576, K=192) ----------------
// blockIdx.y: 0..2 -> W_B (out g_Bm), 3..5 -> W_C (out g_Cm), 6..8 -> W_dt (out delta/du)
__global__ void proj_kernel(const float* __restrict__ W_B, const float* __restrict__ b_B,
                            const float* __restrict__ W_C, const float* __restrict__ b_C,
                            const float* __restrict__ W_dt, const float* __restrict__ b_dt) {
    __shared__ __align__(16) float As[16][128];  // [k][m]
    __shared__ __align__(16) float Bs[16][64];   // [k][n]

    int tid = threadIdx.x;
    int tx = tid & 15;      // n-dir
    int ty = tid >> 4;      // m-dir
    int m0 = blockIdx.x * 128;
    int by = blockIdx.y;

    const float* W; const float* bias; int off;
    if (by < 3)      { W = W_B;  bias = b_B;  off = 0;   }
    else if (by < 6) { W = W_C;  bias = b_C;  off = 192; }
    else             { W = W_dt; bias = b_dt; off = 384; }
    int jr  = by * 64;
    int jw0 = jr - off;     // local column base within this weight matrix

    float acc[8][4];
#pragma unroll
    for (int i = 0; i < 8; i++)
#pragma unroll
        for (int j = 0; j < 4; j++) acc[i][j] = 0.0f;

    for (int kt = 0; kt < 12; kt++) {
        int k0 = kt * 16;
        // load A tile 128x16 (transposed into smem)
#pragma unroll
        for (int r = 0; r < 2; r++) {
            int idx  = tid + r * 256;
            int mrow = idx >> 2;
            int kq   = idx & 3;
            float4 v = *(const float4*)&g_tokens[(m0 + mrow) * 192 + k0 + kq * 4];
            As[kq * 4 + 0][mrow] = v.x;
            As[kq * 4 + 1][mrow] = v.y;
            As[kq * 4 + 2][mrow] = v.z;
            As[kq * 4 + 3][mrow] = v.w;
        }
        // load B tile 16x64 from W[j][k]
        {
            int jrow = tid >> 2;
            int kq   = tid & 3;
            float4 v = *(const float4*)&W[(jw0 + jrow) * 192 + k0 + kq * 4];
            Bs[kq * 4 + 0][jrow] = v.x;
            Bs[kq * 4 + 1][jrow] = v.y;
            Bs[kq * 4 + 2][jrow] = v.z;
            Bs[kq * 4 + 3][jrow] = v.w;
        }
        __syncthreads();
#pragma unroll
        for (int kk = 0; kk < 16; kk++) {
            float4 a0 = *(const float4*)&As[kk][ty * 8];
            float4 a1 = *(const float4*)&As[kk][ty * 8 + 4];
            float4 bv = *(const float4*)&Bs[kk][tx * 4];
            float a[8] = {a0.x, a0.y, a0.z, a0.w, a1.x, a1.y, a1.z, a1.w};
            float bb[4] = {bv.x, bv.y, bv.z, bv.w};
#pragma unroll
            for (int i = 0; i < 8; i++)
#pragma unroll
                for (int j = 0; j < 4; j++) acc[i][j] = fmaf(a[i], bb[j], acc[i][j]);
        }
        __syncthreads();
    }

    int ncol = jw0 + tx * 4;   // local feature index within the 192-wide output
    if (by < 6) {
        float4 bv4 = *(const float4*)&bias[ncol];
        float* dst = (by < 3) ? g_Bm : g_Cm;
#pragma unroll
        for (int i = 0; i < 8; i++) {
            int m = m0 + ty * 8 + i;
            float4 o;
            o.x = acc[i][0] + bv4.x;
            o.y = acc[i][1] + bv4.y;
            o.z = acc[i][2] + bv4.z;
            o.w = acc[i][3] + bv4.w;
            *(float4*)&dst[m * 192 + ncol] = o;
        }
    } else {
        float bd[4];
#pragma unroll
        for (int j = 0; j < 4; j++) bd[j] = bias[ncol + j];
#pragma unroll
        for (int i = 0; i < 8; i++) {
            int m = m0 + ty * 8 + i;
            int b = m >> 12;
            int l = m & 4095;
#pragma unroll
            for (int j = 0; j < 4; j++) {
                int dfeat = ncol + j;
                float lin = acc[i][j] + bd[j];
                float dt  = softplus_f(lin);
                float del = softplus_f(dt + bd[j]);   // selective_scan applies softplus(+bias) again
                float u   = g_tokens[m * 192 + dfeat];
                int o = (b * 192 + dfeat) * LSEQ + l;
                g_deltaT[o] = del;
                g_duT[o]    = del * u;
            }
        }
    }
}

// ---------------- K2: selective scan ----------------
// 1 warp per (b,d); 6 states per lane (n = lane + 32*j).
// B/C rows staged in smem in 16-step double-buffered chunks (cp.async).
#define CH 16
__global__ void scan_kernel(const float* __restrict__ A_log, const float* __restrict__ Dp,
                            float* __restrict__ out) {
    extern __shared__ __align__(16) float S[];   // [2 buf][B:3072 | C:3072] = 12288 floats = 48KB

    int tid  = threadIdx.x;
    int warp = tid >> 5;
    int lane = tid & 31;
    int b = blockIdx.x / 48;
    int d = (blockIdx.x % 48) * 4 + warp;

    float A2[6], h[6];
#pragma unroll
    for (int j = 0; j < 6; j++) {
        int n = lane + 32 * j;
        A2[j] = -expf(A_log[d * 192 + n]) * 1.4426950408889634f;   // A * log2(e)
        h[j]  = 0.0f;
    }
    float dpar = Dp[d];
    const float SILU1 = 0.73105857863000489f;  // 1*sigmoid(1)

    const float* Brow  = g_Bm + b * LSEQ * 192;
    const float* Crow  = g_Cm + b * LSEQ * 192;
    const float* dptr  = g_deltaT + (b * 192 + d) * LSEQ;
    const float* duptr = g_duT    + (b * 192 + d) * LSEQ;
    const float* uptr  = g_uT     + (b * 192 + d) * LSEQ;

    // prologue: chunk 0
    {
        float* Sb = S;
        float* Sc = S + 3072;
#pragma unroll
        for (int q = 0; q < 6; q++) {
            int off = (tid + q * 128) * 4;
            cp16(Sb + off, Brow + off);
            cp16(Sc + off, Crow + off);
        }
        cp_commit();
        cp_wait0();
    }
    __syncthreads();

    float dv = 0.0f, duv = 0.0f, uv = 0.0f;

    for (int c = 0; c < LSEQ / CH; c++) {
        int l0  = c * CH;
        int buf = c & 1;
        if (c + 1 < LSEQ / CH) {
            float* Sb = S + (buf ^ 1) * 6144;
            float* Sc = Sb + 3072;
            const float* bsrc = Brow + (l0 + CH) * 192;
            const float* csrc = Crow + (l0 + CH) * 192;
#pragma unroll
            for (int q = 0; q < 6; q++) {
                int off = (tid + q * 128) * 4;
                cp16(Sb + off, bsrc + off);
                cp16(Sc + off, csrc + off);
            }
            cp_commit();
        }
        const float* bs = S + buf * 6144;
        const float* cs = bs + 3072;

        for (int s = 0; s < CH; s++) {
            int l = l0 + s;
            if ((l & 31) == 0) {          // warp-uniform
                dv  = dptr[l + lane];
                duv = duptr[l + lane];
                uv  = uptr[l + lane];
            }
            int sl = l & 31;
            float del = __shfl_sync(0xffffffffu, dv,  sl);
            float du  = __shfl_sync(0xffffffffu, duv, sl);
            float uu  = __shfl_sync(0xffffffffu, uv,  sl);

            float acc = 0.0f;
            const float* bp = bs + s * 192;
            const float* cp = cs + s * 192;
#pragma unroll
            for (int j = 0; j < 6; j++) {
                int n = lane + 32 * j;
                float e = ex2f(del * A2[j]);
                h[j] = fmaf(e, h[j], du * bp[n]);
                acc  = fmaf(h[j], cp[n], acc);
            }
            acc += __shfl_xor_sync(0xffffffffu, acc, 16);
            acc += __shfl_xor_sync(0xffffffffu, acc, 8);
            acc += __shfl_xor_sync(0xffffffffu, acc, 4);
            acc += __shfl_xor_sync(0xffffffffu, acc, 2);
            acc += __shfl_xor_sync(0xffffffffu, acc, 1);

            if (lane == 0) {
                float val = (acc + dpar * uu) * SILU1;
                // reference's output reshape: flat = d*L + l -> (64,64,48,2,2) -> transpose(0,3,1,4,2,5)
                int flat = d * LSEQ + l;
                int i1   = flat / 12288;
                int rem  = flat - i1 * 12288;
                int i2   = rem / 192;
                int r2   = rem - i2 * 192;
                int i3   = r2 >> 2;
                int i4   = (r2 >> 1) & 1;
                int i5   = r2 & 1;
                out[((b * 48 + i3) * 128 + i1 * 2 + i4) * 128 + i2 * 2 + i5] = val;
            }
        }
        cp_wait0();
        __syncthreads();
    }
}

// ---------------- launch ----------------
extern "C" void kernel_launch(void* const* d_in, const int* in_sizes, int n_in,
                              void* d_out, int out_size) {
    (void)in_sizes; (void)n_in; (void)out_size;
    const float* x     = (const float*)d_in[0];
    const float* A_log = (const float*)d_in[1];
    const float* Dp    = (const float*)d_in[2];
    const float* W_B   = (const float*)d_in[3];
    const float* b_B   = (const float*)d_in[4];
    const float* W_C   = (const float*)d_in[5];
    const float* b_C   = (const float*)d_in[6];
    const float* W_dt  = (const float*)d_in[7];
    const float* b_dt  = (const float*)d_in[8];
    float* out = (float*)d_out;

    remap_kernel<<<(TOT + 255) / 256, 256>>>(x);
    dim3 g(64, 9);
    proj_kernel<<<g, 256>>>(W_B, b_B, W_C, b_C, W_dt, b_dt);
    scan_kernel<<<96, 128, 2 * 2 * CH * 192 * (int)sizeof(float)>>>(A_log, Dp, out);
}

// round 3
// speedup vs baseline: 3.4706x; 3.4706x over previous
#include <cuda_runtime.h>
#include <math.h>

// Problem constants
#define LSEQ 4096
#define DD   192
#define BB   2
#define TOT  (BB*LSEQ*DD)   // 1,572,864

// ---------------- scratch (no allocations allowed) ----------------
__device__ __align__(16) float g_tokens[TOT];  // [b][l][d]
__device__ __align__(16) float g_uT[TOT];      // [b][d][l]
__device__ __align__(16) float g_Bm[TOT];      // [b][l][n]
__device__ __align__(16) float g_Cm[TOT];      // [b][l][n]
__device__ __align__(16) float g_deltaT[TOT];  // [b][d][l]
__device__ __align__(16) float g_duT[TOT];     // [b][d][l]

// ---------------- helpers ----------------
__device__ __forceinline__ float ex2f(float x) {
    float y;
    asm("ex2.approx.ftz.f32 %0, %1;" : "=f"(y) : "f"(x));
    return y;
}

__device__ __forceinline__ float softplus_f(float x) {
    if (x > 20.0f) return x;
    return log1pf(expf(x));
}

__device__ __forceinline__ void cp16(float* smem_dst, const float* gmem_src) {
    unsigned s = (unsigned)__cvta_generic_to_shared(smem_dst);
    asm volatile("cp.async.cg.shared.global [%0], [%1], 16;\n" :: "r"(s), "l"(gmem_src));
}
__device__ __forceinline__ void cp_commit() { asm volatile("cp.async.commit_group;\n" ::: "memory"); }
__device__ __forceinline__ void cp_wait0()  { asm volatile("cp.async.wait_group 0;\n" ::: "memory"); }

// ---------------- K0: tokenize (window unfold) ----------------
__global__ void remap_kernel(const float* __restrict__ x) {
    int idx = blockIdx.x * 256 + threadIdx.x;
    if (idx >= TOT) return;
    int d = idx % DD;
    int l = (idx / DD) & (LSEQ - 1);
    int b = idx / (DD * LSEQ);
    int c  = d >> 2;
    int dy = (d >> 1) & 1;
    int dx = d & 1;
    int ih = l >> 6;
    int iw = l & 63;
    float v = x[((b * 48 + c) * 128 + (ih * 2 + dy)) * 128 + (iw * 2 + dx)];
    g_tokens[idx] = v;
    g_uT[(b * DD + d) * LSEQ + l] = v;
}

// ---------------- K1: fused projections (unchanged) ----------------
__global__ void proj_kernel(const float* __restrict__ W_B, const float* __restrict__ b_B,
                            const float* __restrict__ W_C, const float* __restrict__ b_C,
                            const float* __restrict__ W_dt, const float* __restrict__ b_dt) {
    __shared__ __align__(16) float As[16][128];
    __shared__ __align__(16) float Bs[16][64];

    int tid = threadIdx.x;
    int tx = tid & 15;
    int ty = tid >> 4;
    int m0 = blockIdx.x * 128;
    int by = blockIdx.y;

    const float* W; const float* bias; int off;
    if (by < 3)      { W = W_B;  bias = b_B;  off = 0;   }
    else if (by < 6) { W = W_C;  bias = b_C;  off = 192; }
    else             { W = W_dt; bias = b_dt; off = 384; }
    int jw0 = by * 64 - off;

    float acc[8][4];
#pragma unroll
    for (int i = 0; i < 8; i++)
#pragma unroll
        for (int j = 0; j < 4; j++) acc[i][j] = 0.0f;

    for (int kt = 0; kt < 12; kt++) {
        int k0 = kt * 16;
#pragma unroll
        for (int r = 0; r < 2; r++) {
            int idx  = tid + r * 256;
            int mrow = idx >> 2;
            int kq   = idx & 3;
            float4 v = *(const float4*)&g_tokens[(m0 + mrow) * 192 + k0 + kq * 4];
            As[kq * 4 + 0][mrow] = v.x;
            As[kq * 4 + 1][mrow] = v.y;
            As[kq * 4 + 2][mrow] = v.z;
            As[kq * 4 + 3][mrow] = v.w;
        }
        {
            int jrow = tid >> 2;
            int kq   = tid & 3;
            float4 v = *(const float4*)&W[(jw0 + jrow) * 192 + k0 + kq * 4];
            Bs[kq * 4 + 0][jrow] = v.x;
            Bs[kq * 4 + 1][jrow] = v.y;
            Bs[kq * 4 + 2][jrow] = v.z;
            Bs[kq * 4 + 3][jrow] = v.w;
        }
        __syncthreads();
#pragma unroll
        for (int kk = 0; kk < 16; kk++) {
            float4 a0 = *(const float4*)&As[kk][ty * 8];
            float4 a1 = *(const float4*)&As[kk][ty * 8 + 4];
            float4 bv = *(const float4*)&Bs[kk][tx * 4];
            float a[8] = {a0.x, a0.y, a0.z, a0.w, a1.x, a1.y, a1.z, a1.w};
            float bb[4] = {bv.x, bv.y, bv.z, bv.w};
#pragma unroll
            for (int i = 0; i < 8; i++)
#pragma unroll
                for (int j = 0; j < 4; j++) acc[i][j] = fmaf(a[i], bb[j], acc[i][j]);
        }
        __syncthreads();
    }

    int ncol = jw0 + tx * 4;
    if (by < 6) {
        float4 bv4 = *(const float4*)&bias[ncol];
        float* dst = (by < 3) ? g_Bm : g_Cm;
#pragma unroll
        for (int i = 0; i < 8; i++) {
            int m = m0 + ty * 8 + i;
            float4 o;
            o.x = acc[i][0] + bv4.x;
            o.y = acc[i][1] + bv4.y;
            o.z = acc[i][2] + bv4.z;
            o.w = acc[i][3] + bv4.w;
            *(float4*)&dst[m * 192 + ncol] = o;
        }
    } else {
        float bd[4];
#pragma unroll
        for (int j = 0; j < 4; j++) bd[j] = bias[ncol + j];
#pragma unroll
        for (int i = 0; i < 8; i++) {
            int m = m0 + ty * 8 + i;
            int b = m >> 12;
            int l = m & 4095;
#pragma unroll
            for (int j = 0; j < 4; j++) {
                int dfeat = ncol + j;
                float lin = acc[i][j] + bd[j];
                float dt  = softplus_f(lin);
                float del = softplus_f(dt + bd[j]);
                float u   = g_tokens[m * 192 + dfeat];
                int o = (b * 192 + dfeat) * LSEQ + l;
                g_deltaT[o] = del;
                g_duT[o]    = del * u;
            }
        }
    }
}

// ---------------- K2: selective scan (shuffle-free) ----------------
// 1 warp per (b,d); 6 states per lane (n = lane + 32*j).
// Per step: read delta/du from smem (uniform), update h, write per-lane partial to smem.
// Per 32-step chunk: transpose-reduce partials (lane s sums row s), fused epilogue, STG.
#define CH 32
#define PSTRIDE 36

__global__ void __launch_bounds__(128, 1)
scan_kernel(const float* __restrict__ A_log, const float* __restrict__ Dp,
            float* __restrict__ out) {
    extern __shared__ __align__(16) float S[];
    // layout: Bbuf[2][CH*192] | Cbuf[2][CH*192] | P[4][CH][PSTRIDE] | DU[4][2][3][CH]
    float* Bbuf  = S;
    float* Cbuf  = S + 2 * CH * 192;
    float* Pbuf  = S + 4 * CH * 192;
    float* DUbuf = Pbuf + 4 * CH * PSTRIDE;

    int tid  = threadIdx.x;
    int warp = tid >> 5;
    int lane = tid & 31;
    int b = blockIdx.x / 48;
    int d = (blockIdx.x % 48) * 4 + warp;

    float A2[6], h[6];
#pragma unroll
    for (int j = 0; j < 6; j++) {
        int n = lane + 32 * j;
        A2[j] = -expf(A_log[d * 192 + n]) * 1.4426950408889634f;
        h[j]  = 0.0f;
    }
    float dpar = Dp[d];
    const float SILU1 = 0.73105857863000489f;

    const float* Brow  = g_Bm + b * LSEQ * 192;
    const float* Crow  = g_Cm + b * LSEQ * 192;
    const float* dptr  = g_deltaT + (b * 192 + d) * LSEQ;
    const float* duptr = g_duT    + (b * 192 + d) * LSEQ;
    const float* uptr  = g_uT     + (b * 192 + d) * LSEQ;

    float* Pw  = Pbuf + warp * CH * PSTRIDE;
    float* DUw = DUbuf + warp * 2 * 3 * CH;

    // prologue: chunk 0 B/C via cp.async; chunk 0 delta/du/u via LDG->STS
    {
#pragma unroll
        for (int q = 0; q < 12; q++) {
            int off = (tid + q * 128) * 4;
            cp16(Bbuf + off, Brow + off);
            cp16(Cbuf + off, Crow + off);
        }
        cp_commit();
        float dn = dptr[lane], dun = duptr[lane], un = uptr[lane];
        DUw[lane]          = dn;
        DUw[CH + lane]     = dun;
        DUw[2 * CH + lane] = un;
        cp_wait0();
    }
    __syncthreads();

    const int NCHUNK = LSEQ / CH;
    for (int c = 0; c < NCHUNK; c++) {
        int l0  = c * CH;
        int buf = c & 1;

        float dn = 0.f, dun = 0.f, un = 0.f;
        if (c + 1 < NCHUNK) {
            // prefetch next B/C
            float* Sb = Bbuf + (buf ^ 1) * (CH * 192);
            float* Sc = Cbuf + (buf ^ 1) * (CH * 192);
            const float* bsrc = Brow + (l0 + CH) * 192;
            const float* csrc = Crow + (l0 + CH) * 192;
#pragma unroll
            for (int q = 0; q < 12; q++) {
                int off = (tid + q * 128) * 4;
                cp16(Sb + off, bsrc + off);
                cp16(Sc + off, csrc + off);
            }
            cp_commit();
            // prefetch next delta/du/u into registers
            dn  = dptr[l0 + CH + lane];
            dun = duptr[l0 + CH + lane];
            un  = uptr[l0 + CH + lane];
        }

        const float* bs = Bbuf + buf * (CH * 192);
        const float* cs = Cbuf + buf * (CH * 192);
        const float* dl = DUw + (c & 1) * 0;  // DU single-buffered per warp? -> use explicit buf
        // NOTE: DU is double-buffered below via (c&1)
        const float* dchunk = DUbuf + warp * 2 * 3 * CH + (c & 1) * 3 * CH;

#pragma unroll 4
        for (int s = 0; s < CH; s++) {
            float del = dchunk[s];
            float du  = dchunk[CH + s];
            float acc = 0.0f;
            const float* bp = bs + s * 192 + lane;
            const float* cp = cs + s * 192 + lane;
#pragma unroll
            for (int j = 0; j < 6; j++) {
                float e = ex2f(del * A2[j]);
                h[j] = fmaf(e, h[j], du * bp[32 * j]);
                acc  = fmaf(h[j], cp[32 * j], acc);
            }
            Pw[s * PSTRIDE + lane] = acc;
        }
        __syncwarp();

        // reduce: lane handles step s = lane
        {
            const float* Pr = Pw + lane * PSTRIDE;
            float4 v0 = *(const float4*)&Pr[0];
            float4 v1 = *(const float4*)&Pr[4];
            float4 v2 = *(const float4*)&Pr[8];
            float4 v3 = *(const float4*)&Pr[12];
            float4 v4 = *(const float4*)&Pr[16];
            float4 v5 = *(const float4*)&Pr[20];
            float4 v6 = *(const float4*)&Pr[24];
            float4 v7 = *(const float4*)&Pr[28];
            float s0 = (v0.x + v0.y) + (v0.z + v0.w);
            float s1 = (v1.x + v1.y) + (v1.z + v1.w);
            float s2 = (v2.x + v2.y) + (v2.z + v2.w);
            float s3 = (v3.x + v3.y) + (v3.z + v3.w);
            float s4 = (v4.x + v4.y) + (v4.z + v4.w);
            float s5 = (v5.x + v5.y) + (v5.z + v5.w);
            float s6 = (v6.x + v6.y) + (v6.z + v6.w);
            float s7 = (v7.x + v7.y) + (v7.z + v7.w);
            float sum = ((s0 + s1) + (s2 + s3)) + ((s4 + s5) + (s6 + s7));

            float uu  = dchunk[2 * CH + lane];
            float val = (sum + dpar * uu) * SILU1;

            int l    = l0 + lane;
            int flat = d * LSEQ + l;
            int i1   = flat / 12288;
            int rem  = flat - i1 * 12288;
            int i2   = rem / 192;
            int r2   = rem - i2 * 192;
            int i3   = r2 >> 2;
            int i4   = (r2 >> 1) & 1;
            int i5   = r2 & 1;
            out[((b * 48 + i3) * 128 + i1 * 2 + i4) * 128 + i2 * 2 + i5] = val;
        }

        // store prefetched delta/du/u for next chunk
        if (c + 1 < NCHUNK) {
            float* dnext = DUbuf + warp * 2 * 3 * CH + ((c + 1) & 1) * 3 * CH;
            dnext[lane]          = dn;
            dnext[CH + lane]     = dun;
            dnext[2 * CH + lane] = un;
        }
        (void)dl;
        cp_wait0();
        __syncthreads();
    }
}

// ---------------- launch ----------------
extern "C" void kernel_launch(void* const* d_in, const int* in_sizes, int n_in,
                              void* d_out, int out_size) {
    (void)in_sizes; (void)n_in; (void)out_size;
    const float* x     = (const float*)d_in[0];
    const float* A_log = (const float*)d_in[1];
    const float* Dp    = (const float*)d_in[2];
    const float* W_B   = (const float*)d_in[3];
    const float* b_B   = (const float*)d_in[4];
    const float* W_C   = (const float*)d_in[5];
    const float* b_C   = (const float*)d_in[6];
    const float* W_dt  = (const float*)d_in[7];
    const float* b_dt  = (const float*)d_in[8];
    float* out = (float*)d_out;

    // smem: B/C double buffers + partials + DU staging
    int smem = (4 * CH * 192 + 4 * CH * PSTRIDE + 4 * 2 * 3 * CH) * (int)sizeof(float);
    static int attr_set = 0;
    if (!attr_set) {
        cudaFuncSetAttribute(scan_kernel, cudaFuncAttributeMaxDynamicSharedMemorySize, smem);
        attr_set = 1;
    }

    remap_kernel<<<(TOT + 255) / 256, 256>>>(x);
    dim3 g(64, 9);
    proj_kernel<<<g, 256>>>(W_B, b_B, W_C, b_C, W_dt, b_dt);
    scan_kernel<<<96, 128, smem>>>(A_log, Dp, out);
}

// round 4
// speedup vs baseline: 3.8227x; 1.1015x over previous
#include <cuda_runtime.h>
#include <math.h>

#define LSEQ 4096
#define DD   192
#define BB   2
#define TOT  (BB*LSEQ*DD)

// ---------------- scratch ----------------
__device__ __align__(16) float g_uT[TOT];      // [b][d][l]
__device__ __align__(16) float g_Bm[TOT];      // [b][l][n]
__device__ __align__(16) float g_Cm[TOT];      // [b][l][n]
__device__ __align__(16) float g_deltaT[TOT];  // [b][d][l]
__device__ __align__(16) float g_duT[TOT];     // [b][d][l]

// ---------------- helpers ----------------
__device__ __forceinline__ float ex2f(float x) {
    float y;
    asm("ex2.approx.ftz.f32 %0, %1;" : "=f"(y) : "f"(x));
    return y;
}
__device__ __forceinline__ float softplus_f(float x) {
    if (x > 20.0f) return x;
    return log1pf(expf(x));
}
__device__ __forceinline__ void cp16(float* smem_dst, const float* gmem_src) {
    unsigned s = (unsigned)__cvta_generic_to_shared(smem_dst);
    asm volatile("cp.async.cg.shared.global [%0], [%1], 16;\n" :: "r"(s), "l"(gmem_src));
}
__device__ __forceinline__ void cp_commit() { asm volatile("cp.async.commit_group;\n" ::: "memory"); }
__device__ __forceinline__ void cp_wait0()  { asm volatile("cp.async.wait_group 0;\n" ::: "memory"); }

// ---------------- K1: fused tokenize + projections ----------------
// A-matrix rows gathered directly from x (window unfold done in the loader).
__global__ void proj_kernel(const float* __restrict__ x,
                            const float* __restrict__ W_B, const float* __restrict__ b_B,
                            const float* __restrict__ W_C, const float* __restrict__ b_C,
                            const float* __restrict__ W_dt, const float* __restrict__ b_dt) {
    __shared__ __align__(16) float As[16][128];
    __shared__ __align__(16) float Bs[16][64];

    int tid = threadIdx.x;
    int tx = tid & 15;
    int ty = tid >> 4;
    int m0 = blockIdx.x * 128;
    int by = blockIdx.y;

    const float* W; const float* bias; int off;
    if (by < 3)      { W = W_B;  bias = b_B;  off = 0;   }
    else if (by < 6) { W = W_C;  bias = b_C;  off = 192; }
    else             { W = W_dt; bias = b_dt; off = 384; }
    int jw0 = by * 64 - off;

    float acc[8][4];
#pragma unroll
    for (int i = 0; i < 8; i++)
#pragma unroll
        for (int j = 0; j < 4; j++) acc[i][j] = 0.0f;

    for (int kt = 0; kt < 12; kt++) {
        int k0 = kt * 16;
        // A tile 128x16 gathered from x: k = c*4 + dy*2 + dx
#pragma unroll
        for (int r = 0; r < 2; r++) {
            int idx  = tid + r * 256;
            int mrow = idx >> 2;
            int kq   = idx & 3;
            int m = m0 + mrow;
            int b = m >> 12;
            int l = m & 4095;
            int ih = l >> 6;
            int iw = l & 63;
            int c  = (k0 >> 2) + kq;
            const float* xb = x + (((b * 48 + c) * 128 + ih * 2) * 128 + iw * 2);
            float2 v01 = *(const float2*)xb;
            float2 v23 = *(const float2*)(xb + 128);
            As[kq * 4 + 0][mrow] = v01.x;
            As[kq * 4 + 1][mrow] = v01.y;
            As[kq * 4 + 2][mrow] = v23.x;
            As[kq * 4 + 3][mrow] = v23.y;
        }
        {
            int jrow = tid >> 2;
            int kq   = tid & 3;
            float4 v = *(const float4*)&W[(jw0 + jrow) * 192 + k0 + kq * 4];
            Bs[kq * 4 + 0][jrow] = v.x;
            Bs[kq * 4 + 1][jrow] = v.y;
            Bs[kq * 4 + 2][jrow] = v.z;
            Bs[kq * 4 + 3][jrow] = v.w;
        }
        __syncthreads();
#pragma unroll
        for (int kk = 0; kk < 16; kk++) {
            float4 a0 = *(const float4*)&As[kk][ty * 8];
            float4 a1 = *(const float4*)&As[kk][ty * 8 + 4];
            float4 bv = *(const float4*)&Bs[kk][tx * 4];
            float a[8] = {a0.x, a0.y, a0.z, a0.w, a1.x, a1.y, a1.z, a1.w};
            float bb[4] = {bv.x, bv.y, bv.z, bv.w};
#pragma unroll
            for (int i = 0; i < 8; i++)
#pragma unroll
                for (int j = 0; j < 4; j++) acc[i][j] = fmaf(a[i], bb[j], acc[i][j]);
        }
        __syncthreads();
    }

    int ncol = jw0 + tx * 4;
    if (by < 6) {
        float4 bv4 = *(const float4*)&bias[ncol];
        float* dst = (by < 3) ? g_Bm : g_Cm;
#pragma unroll
        for (int i = 0; i < 8; i++) {
            int m = m0 + ty * 8 + i;
            float4 o;
            o.x = acc[i][0] + bv4.x;
            o.y = acc[i][1] + bv4.y;
            o.z = acc[i][2] + bv4.z;
            o.w = acc[i][3] + bv4.w;
            *(float4*)&dst[m * 192 + ncol] = o;
        }
    } else {
        float bd[4];
#pragma unroll
        for (int j = 0; j < 4; j++) bd[j] = bias[ncol + j];
        int c2 = ncol >> 2;
#pragma unroll
        for (int i = 0; i < 8; i++) {
            int m = m0 + ty * 8 + i;
            int b = m >> 12;
            int l = m & 4095;
            int ih = l >> 6;
            int iw = l & 63;
            const float* xb = x + (((b * 48 + c2) * 128 + ih * 2) * 128 + iw * 2);
            float uvals[4];
            uvals[0] = xb[0];
            uvals[1] = xb[1];
            uvals[2] = xb[128];
            uvals[3] = xb[129];
#pragma unroll
            for (int j = 0; j < 4; j++) {
                int dfeat = ncol + j;
                float lin = acc[i][j] + bd[j];
                float dt  = softplus_f(lin);
                float del = softplus_f(dt + bd[j]);
                float u   = uvals[j];
                int o = (b * 192 + dfeat) * LSEQ + l;
                g_deltaT[o] = del;
                g_duT[o]    = del * u;
                g_uT[o]     = u;
            }
        }
    }
}

// ---------------- K2: selective scan, 2-way N-split ----------------
// Block = 256 threads = 8 warps: pair p = warp&3 (d = dbase+p), half = warp>>2.
// Each warp owns 96 states (3/lane, n = half*96 + lane + 32j).
#define CH 32
#define PSTR 68

__global__ void __launch_bounds__(256, 1)
scan_kernel(const float* __restrict__ A_log, const float* __restrict__ Dp,
            float* __restrict__ out) {
    extern __shared__ __align__(16) float S[];
    float* Bbuf  = S;                           // [2][CH*192]
    float* Cbuf  = S + 2 * CH * 192;            // [2][CH*192]
    float* Pbuf  = S + 4 * CH * 192;            // [4][CH][PSTR]
    float* DUbuf = Pbuf + 4 * CH * PSTR;        // [4][2][3][CH]

    int tid  = threadIdx.x;
    int warp = tid >> 5;
    int lane = tid & 31;
    int pair = warp & 3;
    int half = warp >> 2;
    int noff = half * 96;
    int b = blockIdx.x / 48;
    int d = (blockIdx.x % 48) * 4 + pair;

    float A2[3], h[3];
#pragma unroll
    for (int j = 0; j < 3; j++) {
        int n = noff + lane + 32 * j;
        A2[j] = -expf(A_log[d * 192 + n]) * 1.4426950408889634f;
        h[j]  = 0.0f;
    }
    float dpar = Dp[d];
    const float SILU1 = 0.73105857863000489f;

    const float* Brow  = g_Bm + b * LSEQ * 192;
    const float* Crow  = g_Cm + b * LSEQ * 192;
    const float* dptr  = g_deltaT + (b * 192 + d) * LSEQ;
    const float* duptr = g_duT    + (b * 192 + d) * LSEQ;
    const float* uptr  = g_uT     + (b * 192 + d) * LSEQ;

    float* Pw = Pbuf + pair * CH * PSTR;

    // prologue: chunk 0
    {
#pragma unroll
        for (int q = 0; q < 6; q++) {
            int off = (tid + q * 256) * 4;
            cp16(Bbuf + off, Brow + off);
            cp16(Cbuf + off, Crow + off);
        }
        cp_commit();
        if (half == 0) {
            float* DU0 = DUbuf + pair * 2 * 3 * CH;
            DU0[lane]          = dptr[lane];
            DU0[CH + lane]     = duptr[lane];
            DU0[2 * CH + lane] = uptr[lane];
        }
        cp_wait0();
    }
    __syncthreads();

    const int NCHUNK = LSEQ / CH;
    for (int c = 0; c < NCHUNK; c++) {
        int l0  = c * CH;
        int buf = c & 1;

        float dn = 0.f, dun = 0.f, un = 0.f;
        if (c + 1 < NCHUNK) {
            float* Sb = Bbuf + (buf ^ 1) * (CH * 192);
            float* Sc = Cbuf + (buf ^ 1) * (CH * 192);
            const float* bsrc = Brow + (l0 + CH) * 192;
            const float* csrc = Crow + (l0 + CH) * 192;
#pragma unroll
            for (int q = 0; q < 6; q++) {
                int off = (tid + q * 256) * 4;
                cp16(Sb + off, bsrc + off);
                cp16(Sc + off, csrc + off);
            }
            cp_commit();
            if (half == 0) {
                dn  = dptr[l0 + CH + lane];
                dun = duptr[l0 + CH + lane];
                un  = uptr[l0 + CH + lane];
            }
        }

        const float* bs = Bbuf + buf * (CH * 192) + noff + lane;
        const float* cs = Cbuf + buf * (CH * 192) + noff + lane;
        const float* dchunk = DUbuf + pair * 2 * 3 * CH + buf * 3 * CH;
        float* Pline = Pw + half * 36 + lane;

#pragma unroll 4
        for (int s = 0; s < CH; s++) {
            float del = dchunk[s];
            float du  = dchunk[CH + s];
            const float* bp = bs + s * 192;
            const float* cp = cs + s * 192;
            float acc = 0.0f;
#pragma unroll
            for (int j = 0; j < 3; j++) {
                float e = ex2f(del * A2[j]);
                h[j] = fmaf(e, h[j], du * bp[32 * j]);
                acc  = fmaf(h[j], cp[32 * j], acc);
            }
            Pline[s * PSTR] = acc;
        }
        __syncthreads();

        if (half == 0) {
            // lane s reduces P row s: 64 partials (two halves)
            const float* Pr = Pw + lane * PSTR;
            float sum;
            {
                float4 v0 = *(const float4*)&Pr[0];
                float4 v1 = *(const float4*)&Pr[4];
                float4 v2 = *(const float4*)&Pr[8];
                float4 v3 = *(const float4*)&Pr[12];
                float4 v4 = *(const float4*)&Pr[16];
                float4 v5 = *(const float4*)&Pr[20];
                float4 v6 = *(const float4*)&Pr[24];
                float4 v7 = *(const float4*)&Pr[28];
                float4 w0 = *(const float4*)&Pr[36];
                float4 w1 = *(const float4*)&Pr[40];
                float4 w2 = *(const float4*)&Pr[44];
                float4 w3 = *(const float4*)&Pr[48];
                float4 w4 = *(const float4*)&Pr[52];
                float4 w5 = *(const float4*)&Pr[56];
                float4 w6 = *(const float4*)&Pr[60];
                float4 w7 = *(const float4*)&Pr[64];
                float s0 = (v0.x + v0.y) + (v0.z + v0.w);
                float s1 = (v1.x + v1.y) + (v1.z + v1.w);
                float s2 = (v2.x + v2.y) + (v2.z + v2.w);
                float s3 = (v3.x + v3.y) + (v3.z + v3.w);
                float s4 = (v4.x + v4.y) + (v4.z + v4.w);
                float s5 = (v5.x + v5.y) + (v5.z + v5.w);
                float s6 = (v6.x + v6.y) + (v6.z + v6.w);
                float s7 = (v7.x + v7.y) + (v7.z + v7.w);
                float t0 = (w0.x + w0.y) + (w0.z + w0.w);
                float t1 = (w1.x + w1.y) + (w1.z + w1.w);
                float t2 = (w2.x + w2.y) + (w2.z + w2.w);
                float t3 = (w3.x + w3.y) + (w3.z + w3.w);
                float t4 = (w4.x + w4.y) + (w4.z + w4.w);
                float t5 = (w5.x + w5.y) + (w5.z + w5.w);
                float t6 = (w6.x + w6.y) + (w6.z + w6.w);
                float t7 = (w7.x + w7.y) + (w7.z + w7.w);
                sum = (((s0 + s1) + (s2 + s3)) + ((s4 + s5) + (s6 + s7)))
                    + (((t0 + t1) + (t2 + t3)) + ((t4 + t5) + (t6 + t7)));
            }
            float uu  = dchunk[2 * CH + lane];
            float val = (sum + dpar * uu) * SILU1;

            int l    = l0 + lane;
            int flat = d * LSEQ + l;
            int i1   = flat / 12288;
            int rem  = flat - i1 * 12288;
            int i2   = rem / 192;
            int r2   = rem - i2 * 192;
            int i3   = r2 >> 2;
            int i4   = (r2 >> 1) & 1;
            int i5   = r2 & 1;
            out[((b * 48 + i3) * 128 + i1 * 2 + i4) * 128 + i2 * 2 + i5] = val;

            if (c + 1 < NCHUNK) {
                float* dnext = DUbuf + pair * 2 * 3 * CH + ((c + 1) & 1) * 3 * CH;
                dnext[lane]          = dn;
                dnext[CH + lane]     = dun;
                dnext[2 * CH + lane] = un;
            }
        }
        cp_wait0();
        __syncthreads();
    }
}

// ---------------- launch ----------------
extern "C" void kernel_launch(void* const* d_in, const int* in_sizes, int n_in,
                              void* d_out, int out_size) {
    (void)in_sizes; (void)n_in; (void)out_size;
    const float* x     = (const float*)d_in[0];
    const float* A_log = (const float*)d_in[1];
    const float* Dp    = (const float*)d_in[2];
    const float* W_B   = (const float*)d_in[3];
    const float* b_B   = (const float*)d_in[4];
    const float* W_C   = (const float*)d_in[5];
    const float* b_C   = (const float*)d_in[6];
    const float* W_dt  = (const float*)d_in[7];
    const float* b_dt  = (const float*)d_in[8];
    float* out = (float*)d_out;

    int smem = (4 * CH * 192 + 4 * CH * PSTR + 4 * 2 * 3 * CH) * (int)sizeof(float);
    static int attr_set = 0;
    if (!attr_set) {
        cudaFuncSetAttribute(scan_kernel, cudaFuncAttributeMaxDynamicSharedMemorySize, smem);
        attr_set = 1;
    }

    dim3 g(64, 9);
    proj_kernel<<<g, 256>>>(x, W_B, b_B, W_C, b_C, W_dt, b_dt);
    scan_kernel<<<96, 256, smem>>>(A_log, Dp, out);
}